// round 17
// baseline (speedup 1.0000x reference)
#include <cuda_runtime.h>
#include <cuda_bf16.h>

#define BB 2
#define TT 16
#define DD 64
#define HW 4096
#define NELEM 8388608   // B*T*D*H*W

typedef unsigned long long u64;

// ---------------- packed fp32x2 helpers (SASS FFMA2/FADD2) --------------------
__device__ __forceinline__ u64 pack2(float lo, float hi) {
    u64 r; asm("mov.b64 %0, {%1, %2};" : "=l"(r) : "f"(lo), "f"(hi)); return r;
}
__device__ __forceinline__ u64 pdup(float v) { return pack2(v, v); }
__device__ __forceinline__ float2 unpk(u64 v) {
    float2 f; asm("mov.b64 {%0, %1}, %2;" : "=f"(f.x), "=f"(f.y) : "l"(v)); return f;
}
__device__ __forceinline__ u64 ffma2(u64 a, u64 b, u64 c) {
    u64 d; asm("fma.rn.f32x2 %0, %1, %2, %3;" : "=l"(d) : "l"(a), "l"(b), "l"(c)); return d;
}
__device__ __forceinline__ u64 add2(u64 a, u64 b) {
    u64 d; asm("add.rn.f32x2 %0, %1, %2;" : "=l"(d) : "l"(a), "l"(b)); return d;
}
__device__ __forceinline__ u64 sub2(u64 a, u64 b) {   // a - b
    return ffma2(b, 0xBF800000BF800000ull, a);
}

// ---------------- scratch (device globals; no allocation allowed) -------------
__device__ float g_xnr[NELEM], g_xni[NELEM];
__device__ float g_cr [NELEM], g_ci [NELEM];
__device__ float g_x1r[NELEM], g_x1i[NELEM];
__device__ float g_tnr[NELEM], g_tni[NELEM];
__device__ float g_er [NELEM], g_ei [NELEM];
__device__ float g_x2r[NELEM], g_x2i[NELEM];
__device__ float2 g_evo[BB*TT*DD];
__device__ ulonglong2 g_U[64*64*16];    // Winograd-transformed weights [ic][oc][k]

// ---------------- complex layernorm over 128 feats per (bt,hw) ---------------
__global__ void cnorm_kernel(const float* __restrict__ inr, const float* __restrict__ ini,
                             const float* __restrict__ w,   const float* __restrict__ b,
                             float* __restrict__ outr, float* __restrict__ outi)
{
    int p = blockIdx.x * blockDim.x + threadIdx.x;
    int base = (p >> 12) * (DD * HW) + (p & 4095);
    float sum = 0.f, sq = 0.f;
#pragma unroll 8
    for (int d = 0; d < DD; d++) {
        float a = inr[base + d * HW], c = ini[base + d * HW];
        sum += a + c; sq += a * a + c * c;
    }
    float mu = sum * (1.f / 128.f);
    float rs = rsqrtf(sq * (1.f / 128.f) - mu * mu + 1e-5f);
#pragma unroll 8
    for (int d = 0; d < DD; d++) {
        float a = inr[base + d * HW], c = ini[base + d * HW];
        outr[base + d * HW] = (a - mu) * rs * w[d]      + b[d];
        outi[base + d * HW] = (c - mu) * rs * w[DD + d] + b[DD + d];
    }
}

// ---------------- Winograd weight transform U = G g G^T ----------------------
__global__ void wtrans_kernel(const float* __restrict__ wr, const float* __restrict__ wi,
                              ulonglong2* __restrict__ Ug)
{
    int idx = blockIdx.x * 256 + threadIdx.x;   // 4096 = (oc,ic)
    if (idx >= 4096) return;
    int oc = idx >> 6, ic = idx & 63;
    float gr[3][3], gi[3][3];
#pragma unroll
    for (int r = 0; r < 3; r++)
#pragma unroll
        for (int c = 0; c < 3; c++) {
            gr[r][c] = wr[(oc * 64 + ic) * 9 + r * 3 + c];
            gi[r][c] = wi[(oc * 64 + ic) * 9 + r * 3 + c];
        }
    float Tr[4][3], Ti[4][3];
#pragma unroll
    for (int c = 0; c < 3; c++) {
        Tr[0][c] = gr[0][c];
        Tr[1][c] = 0.5f * (gr[0][c] + gr[1][c] + gr[2][c]);
        Tr[2][c] = 0.5f * (gr[0][c] - gr[1][c] + gr[2][c]);
        Tr[3][c] = gr[2][c];
        Ti[0][c] = gi[0][c];
        Ti[1][c] = 0.5f * (gi[0][c] + gi[1][c] + gi[2][c]);
        Ti[2][c] = 0.5f * (gi[0][c] - gi[1][c] + gi[2][c]);
        Ti[3][c] = gi[2][c];
    }
#pragma unroll
    for (int r = 0; r < 4; r++) {
        float ur[4], ui[4];
        ur[0] = Tr[r][0];
        ur[1] = 0.5f * (Tr[r][0] + Tr[r][1] + Tr[r][2]);
        ur[2] = 0.5f * (Tr[r][0] - Tr[r][1] + Tr[r][2]);
        ur[3] = Tr[r][2];
        ui[0] = Ti[r][0];
        ui[1] = 0.5f * (Ti[r][0] + Ti[r][1] + Ti[r][2]);
        ui[2] = 0.5f * (Ti[r][0] - Ti[r][1] + Ti[r][2]);
        ui[3] = Ti[r][2];
#pragma unroll
        for (int j = 0; j < 4; j++)
            Ug[(ic * 64 + oc) * 16 + r * 4 + j] =
                make_ulonglong2(pack2(ur[j], ui[j]), pack2(-ui[j], ur[j]));
    }
}

// ---------------- Winograd F(2x2,3x3) Clifford conv --------------------------
// block = (16x16 out region, 8 oc, bt); 256 threads; 8x8 tiles of 2x2 outputs.
__global__ void __launch_bounds__(256) conv_wino_kernel(
                            const float* __restrict__ xr, const float* __restrict__ xi,
                            const ulonglong2* __restrict__ Ug,
                            const float* __restrict__ br, const float* __restrict__ bi,
                            float* __restrict__ outr, float* __restrict__ outi)
{
    __shared__ u64 sbuf[4096];                        // 32 KB
    u64* s_in  = sbuf;                                 // 18x18 patch, pitch 20 (360)
    u64* s_tmp = sbuf + 384;                           // 64 tiles x pitch 18 (1152)
    u64* sV    = sbuf + 1536;                          // 16 k x pitch 72 (1152)
    ulonglong2* sU = (ulonglong2*)(sbuf + 2816);       // 8 oc x 16 k (256 u64)

    int tid = threadIdx.x;
    int h0 = (blockIdx.x >> 2) * 16, w0 = (blockIdx.x & 3) * 16;
    int oc0 = blockIdx.y * 8;
    int bt  = blockIdx.z;

    int kk = tid >> 4;            // MAC: frequency 0..15
    int g4 = (tid >> 3) & 1;      //      oc quad
    int tg = tid & 7;             //      tile column
    int tt = tid >> 2, qq = tid & 3;           // transform: tile, row/col
    int th_ = tt >> 3, tw_ = tt & 7;

    u64 acc[4][8];
#pragma unroll
    for (int o = 0; o < 4; o++)
#pragma unroll
        for (int j = 0; j < 8; j++) acc[o][j] = 0ull;

    for (int ic = 0; ic < 64; ic++) {
        const float* pr = xr + (bt * 64 + ic) * HW;
        const float* pi = xi + (bt * 64 + ic) * HW;
        for (int idx = tid; idx < 324; idx += 256) {
            int r = idx / 18, c = idx - r * 18;
            int gh = h0 - 1 + r, gw = w0 - 1 + c;
            float vr = 0.f, vi = 0.f;
            if ((unsigned)gh < 64u && (unsigned)gw < 64u) {
                int g = gh * 64 + gw; vr = pr[g]; vi = pi[g];
            }
            s_in[r * 20 + c] = pack2(vr, vi);
        }
        if (tid < 128)    // contiguous slab [ic][oc0..oc0+7][k]
            ((ulonglong2*)sU)[tid] = Ug[(ic * 64 + oc0) * 16 + tid];
        __syncthreads();

        {   // stage 1: W[qq][j] of tile tt  (W = d * B)
            const u64* rowp = &s_in[(2 * th_ + qq) * 20 + 2 * tw_];
            u64 d0 = rowp[0], d1 = rowp[1], d2 = rowp[2], d3 = rowp[3];
            u64* tp = &s_tmp[tt * 18 + qq * 4];
            tp[0] = sub2(d0, d2);
            tp[1] = add2(d1, d2);
            tp[2] = sub2(d2, d1);
            tp[3] = sub2(d1, d3);
        }
        __syncthreads();
        {   // stage 2: V[i][qq] of tile tt  (V = B^T W)
            u64 w0v = s_tmp[tt * 18 + 0 + qq];
            u64 w1v = s_tmp[tt * 18 + 4 + qq];
            u64 w2v = s_tmp[tt * 18 + 8 + qq];
            u64 w3v = s_tmp[tt * 18 + 12 + qq];
            sV[(0 * 4 + qq) * 72 + tt] = sub2(w0v, w2v);
            sV[(1 * 4 + qq) * 72 + tt] = add2(w1v, w2v);
            sV[(2 * 4 + qq) * 72 + tt] = sub2(w2v, w1v);
            sV[(3 * 4 + qq) * 72 + tt] = sub2(w1v, w3v);
        }
        __syncthreads();
        {   // MAC: M[kk][oc][tile] += U * V
            u64 vr2[8], vi2[8];
#pragma unroll
            for (int j = 0; j < 8; j++) {
                float2 v = unpk(sV[kk * 72 + tg + 8 * j]);
                vr2[j] = pdup(v.x); vi2[j] = pdup(v.y);
            }
#pragma unroll
            for (int oo = 0; oo < 4; oo++) {
                ulonglong2 u = sU[(g4 * 4 + oo) * 16 + kk];
#pragma unroll
                for (int j = 0; j < 8; j++) {
                    acc[oo][j] = ffma2(vr2[j], u.x, acc[oo][j]);
                    acc[oo][j] = ffma2(vi2[j], u.y, acc[oo][j]);
                }
            }
        }
        __syncthreads();
    }

    // ---- output transform, two halves of 32 tiles ----
    u64* sM = sbuf;   // [k][oc][tloc] = k*256 + oc*32 + tloc (4096 u64)
    for (int half = 0; half < 2; half++) {
#pragma unroll
        for (int jj = 0; jj < 4; jj++) {
            int j = half * 4 + jj;
            int tloc = tg + 8 * jj;
#pragma unroll
            for (int oo = 0; oo < 4; oo++)
                sM[kk * 256 + (g4 * 4 + oo) * 32 + tloc] = acc[oo][j];
        }
        __syncthreads();
        {
            int ocl = tid >> 5, tloc = tid & 31;
            int t_t = tloc + half * 32;
            int thh = t_t >> 3, tww = t_t & 7;
            u64 M[16];
#pragma unroll
            for (int k = 0; k < 16; k++) M[k] = sM[k * 256 + ocl * 32 + tloc];
            u64 P0[4], P1[4];
#pragma unroll
            for (int j = 0; j < 4; j++) {
                P0[j] = add2(add2(M[j], M[4 + j]), M[8 + j]);
                P1[j] = sub2(sub2(M[4 + j], M[8 + j]), M[12 + j]);
            }
            u64 Y00 = add2(add2(P0[0], P0[1]), P0[2]);
            u64 Y01 = sub2(sub2(P0[1], P0[2]), P0[3]);
            u64 Y10 = add2(add2(P1[0], P1[1]), P1[2]);
            u64 Y11 = sub2(sub2(P1[1], P1[2]), P1[3]);
            int oc = oc0 + ocl;
            float bre = br[oc], bim = bi[oc];
            int rowbase = (bt * 64 + oc) * HW + (h0 + 2 * thh) * 64 + (w0 + 2 * tww);
            float2 y00 = unpk(Y00), y01 = unpk(Y01), y10 = unpk(Y10), y11 = unpk(Y11);
            *(float2*)&outr[rowbase]      = make_float2(y00.x + bre, y01.x + bre);
            *(float2*)&outi[rowbase]      = make_float2(y00.y + bim, y01.y + bim);
            *(float2*)&outr[rowbase + 64] = make_float2(y10.x + bre, y11.x + bre);
            *(float2*)&outi[rowbase + 64] = make_float2(y10.y + bim, y11.y + bim);
        }
        __syncthreads();
    }
}

// ---------------- radix-8 FFT pieces -----------------------------------------
template<int SGN>
__device__ __forceinline__ void dft8(const float2* a, float2* X)
{
    const float C = 0.70710678118654752f;
    float2 b0 = make_float2(a[0].x + a[4].x, a[0].y + a[4].y);
    float2 b1 = make_float2(a[1].x + a[5].x, a[1].y + a[5].y);
    float2 b2 = make_float2(a[2].x + a[6].x, a[2].y + a[6].y);
    float2 b3 = make_float2(a[3].x + a[7].x, a[3].y + a[7].y);
    float2 d0 = make_float2(a[0].x - a[4].x, a[0].y - a[4].y);
    float2 d1 = make_float2(a[1].x - a[5].x, a[1].y - a[5].y);
    float2 d2 = make_float2(a[2].x - a[6].x, a[2].y - a[6].y);
    float2 d3 = make_float2(a[3].x - a[7].x, a[3].y - a[7].y);
    float2 b4 = d0;
    float2 b5 = make_float2(C * (d1.x - SGN * d1.y), C * (d1.y + SGN * d1.x));
    float2 b6 = make_float2(-SGN * d2.y, SGN * d2.x);
    float2 b7 = make_float2(C * (-d3.x - SGN * d3.y), C * (-d3.y + SGN * d3.x));

    float2 c0 = make_float2(b0.x + b2.x, b0.y + b2.y);
    float2 c1 = make_float2(b1.x + b3.x, b1.y + b3.y);
    float2 e0 = make_float2(b0.x - b2.x, b0.y - b2.y);
    float2 e1 = make_float2(b1.x - b3.x, b1.y - b3.y);
    float2 c2 = e0;
    float2 c3 = make_float2(-SGN * e1.y, SGN * e1.x);
    float2 c4 = make_float2(b4.x + b6.x, b4.y + b6.y);
    float2 c5 = make_float2(b5.x + b7.x, b5.y + b7.y);
    float2 e2 = make_float2(b4.x - b6.x, b4.y - b6.y);
    float2 e3 = make_float2(b5.x - b7.x, b5.y - b7.y);
    float2 c6 = e2;
    float2 c7 = make_float2(-SGN * e3.y, SGN * e3.x);

    X[0] = make_float2(c0.x + c1.x, c0.y + c1.y);
    X[4] = make_float2(c0.x - c1.x, c0.y - c1.y);
    X[2] = make_float2(c2.x + c3.x, c2.y + c3.y);
    X[6] = make_float2(c2.x - c3.x, c2.y - c3.y);
    X[1] = make_float2(c4.x + c5.x, c4.y + c5.y);
    X[5] = make_float2(c4.x - c5.x, c4.y - c5.y);
    X[3] = make_float2(c6.x + c7.x, c6.y + c7.y);
    X[7] = make_float2(c6.x - c7.x, c6.y - c7.y);
}

template<int AXIS, int SGN>
__device__ __forceinline__ void fft_pass(float* sRe, float* sIm, const float2* tw,
                                         int line, int t, float scale)
{
#define SLOT(s) ((AXIS == 0) ? (line * 72 + (s)) : ((s) * 72 + line))
    float2 v[8], y[8];
#pragma unroll
    for (int n2 = 0; n2 < 8; n2++) {
        int s = t + 8 * n2;
        v[n2] = make_float2(sRe[SLOT(s)], sIm[SLOT(s)]);
    }
    dft8<SGN>(v, y);
#pragma unroll
    for (int k2 = 1; k2 < 8; k2++) {
        float2 w = tw[t * k2];
        float re = y[k2].x * w.x - y[k2].y * w.y;
        float im = y[k2].x * w.y + y[k2].y * w.x;
        y[k2] = make_float2(re, im);
    }
    __syncthreads();
#pragma unroll
    for (int k2 = 0; k2 < 8; k2++) {
        int s = k2 * 8 + ((t + k2) & 7);
        sRe[SLOT(s)] = y[k2].x; sIm[SLOT(s)] = y[k2].y;
    }
    __syncthreads();
    float2 z[8], Y[8];
#pragma unroll
    for (int n1 = 0; n1 < 8; n1++) {
        int s = t * 8 + ((n1 + t) & 7);
        z[n1] = make_float2(sRe[SLOT(s)], sIm[SLOT(s)]);
    }
    dft8<SGN>(z, Y);
    __syncthreads();
#pragma unroll
    for (int k1 = 0; k1 < 8; k1++) {
        int s = t + 8 * k1;
        sRe[SLOT(s)] = Y[k1].x * scale; sIm[SLOT(s)] = Y[k1].y * scale;
    }
    __syncthreads();
#undef SLOT
}

__global__ void __launch_bounds__(512) spec_kernel(
                            const float* __restrict__ xnr, const float* __restrict__ xni,
                            const float* __restrict__ swr, const float* __restrict__ swi,
                            const float* __restrict__ clr, const float* __restrict__ cli,
                            const float* __restrict__ x0r, const float* __restrict__ x0i,
                            const float* __restrict__ gate,
                            float* __restrict__ outr, float* __restrict__ outi)
{
    __shared__ float sRe[64 * 72];
    __shared__ float sIm[64 * 72];
    __shared__ float2 stwF[64], stwI[64];
    int tid = threadIdx.x;
    int t = tid & 7, line = tid >> 3;
    int bd = blockIdx.x;
    int d = bd & 63;
    int base = bd * HW;

    if (tid < 64) {
        float s, c;
        sincospif((float)tid * (1.f / 32.f), &s, &c);
        stwF[tid] = make_float2(c, -s);
        stwI[tid] = make_float2(c, s);
    }
    for (int i = tid; i < 4096; i += 512) {
        int r = i >> 6, c = i & 63;
        sRe[r * 72 + c] = xnr[base + i];
        sIm[r * 72 + c] = xni[base + i];
    }
    __syncthreads();

    fft_pass<0, -1>(sRe, sIm, stwF, line, t, 1.f);
    fft_pass<1, -1>(sRe, sIm, stwF, line, t, 1.f);

    for (int i = tid; i < 4096; i += 512) {
        int r = i >> 6, c = i & 63;
        float vr = sRe[r * 72 + c], vi = sIm[r * 72 + c];
        float wrv = swr[d * HW + i], wiv = swi[d * HW + i];
        sRe[r * 72 + c] = vr * wrv - vi * wiv;
        sIm[r * 72 + c] = vr * wiv + vi * wrv;
    }
    __syncthreads();

    fft_pass<1, 1>(sRe, sIm, stwI, line, t, 1.f / 64.f);
    fft_pass<0, 1>(sRe, sIm, stwI, line, t, 1.f / 64.f);

    float g = gate[0], og = 1.f - g;
    for (int i = tid; i < 4096; i += 512) {
        int r = i >> 6, c = i & 63;
        int gi = base + i;
        outr[gi] = g * clr[gi] + og * sRe[r * 72 + c] + x0r[gi];
        outi[gi] = g * cli[gi] + og * sIm[r * 72 + c] + x0i[gi];
    }
}

// ---------------- complex projection (FFMA2) ---------------------------------
__global__ void cproj_kernel(const float* __restrict__ xr, const float* __restrict__ xi,
                             const float* __restrict__ Mre, const float* __restrict__ Mim,
                             const float* __restrict__ resr, const float* __restrict__ resi,
                             float* __restrict__ outr, float* __restrict__ outi,
                             int add_resid)
{
    __shared__ ulonglong2 sM[16 * 64];
    int tid = threadIdx.x;
    int oc0 = blockIdx.y * 16;
    for (int i = tid; i < 1024; i += 256) {
        int o = i >> 6, k = i & 63;
        float mre = Mre[(oc0 + o) * 64 + k], mim = Mim[(oc0 + o) * 64 + k];
        sM[i] = make_ulonglong2(pack2(mre, mim), pack2(-mim, mre));
    }
    __syncthreads();
    int p = blockIdx.x * 256 + tid;
    int base = (p >> 12) * (DD * HW) + (p & 4095);
    u64 acc[16];
#pragma unroll
    for (int o = 0; o < 16; o++) acc[o] = 0ull;
    for (int k = 0; k < 64; k++) {
        u64 a2 = pdup(xr[base + k * HW]);
        u64 c2 = pdup(xi[base + k * HW]);
#pragma unroll
        for (int o = 0; o < 16; o++) {
            ulonglong2 m = sM[o * 64 + k];
            acc[o] = ffma2(a2, m.x, acc[o]);
            acc[o] = ffma2(c2, m.y, acc[o]);
        }
    }
#pragma unroll
    for (int o = 0; o < 16; o++) {
        int gi = base + (oc0 + o) * HW;
        float2 v = unpk(acc[o]);
        if (add_resid) { v.x += resr[gi]; v.y += resi[gi]; }
        outr[gi] = v.x; outi[gi] = v.y;
    }
}

// ---------------- evo = exp(lam * dt) ----------------------------------------
__global__ void evo_kernel(const float* __restrict__ dt,
                           const float* __restrict__ lam_re, const float* __restrict__ lam_im,
                           float2* __restrict__ evo)
{
    int i = blockIdx.x * blockDim.x + threadIdx.x;
    if (i >= BB * TT * DD) return;
    int d = i & 63;
    int b = i >> 10, t = (i >> 6) & 15;
    float dtv = dt[b * 16 + t];
    float lre = -log1pf(expf(lam_re[d]));
    float m = expf(lre * dtv);
    float s, c;
    sincosf(lam_im[d] * dtv, &s, &c);
    evo[i] = make_float2(m * c, m * s);
}

// ---------------- diagonal temporal scan over T=16, in place -----------------
__global__ void scan_kernel(float* __restrict__ er, float* __restrict__ ei,
                            const float2* __restrict__ evo)
{
    int idx = blockIdx.x * 256 + threadIdx.x;
    int b = idx >> 18;
    int dhw = idx & 262143;
    int d = dhw >> 12;
    float hr = 0.f, hi = 0.f;
#pragma unroll
    for (int t = 0; t < 16; t++) {
        float2 a = evo[(b * 16 + t) * 64 + d];
        int gi = (b * 16 + t) * (DD * HW) + dhw;
        float xr = er[gi], xv = ei[gi];
        float nr = a.x * hr - a.y * hi + xr;
        float ni = a.x * hi + a.y * hr + xv;
        hr = nr; hi = ni;
        er[gi] = hr; ei[gi] = hi;
    }
}

// ---------------- fused LN + MLP(128->256 gelu ->128) + resid (FFMA2) --------
__global__ void mlp_kernel(const float* __restrict__ x2r, const float* __restrict__ x2i,
                           const float* __restrict__ lnw, const float* __restrict__ lnb,
                           const float* __restrict__ w1,  const float* __restrict__ b1,
                           const float* __restrict__ w2,  const float* __restrict__ b2,
                           float* __restrict__ out)
{
    __shared__ __align__(16) float smem[12288];  // 48 KB
    float* sZ = smem;            // [128 feat][32 pos]
    float* sH = smem + 4096;     // [32 pos][256 hid]
    int tid = threadIdx.x;
    int p0 = blockIdx.x * 32;
    int base = (p0 >> 12) * (DD * HW) + (p0 & 4095);

    for (int i = tid; i < 2048; i += 256) {
        int d = i >> 5, p = i & 31;
        sZ[d * 32 + p]        = x2r[base + d * HW + p];
        sZ[(64 + d) * 32 + p] = x2i[base + d * HW + p];
    }
    __syncthreads();
    {
        int p = tid >> 3, l = tid & 7;
        float sum = 0.f, sq = 0.f;
#pragma unroll
        for (int c = l; c < 128; c += 8) { float v = sZ[c * 32 + p]; sum += v; sq += v * v; }
#pragma unroll
        for (int m = 1; m < 8; m <<= 1) {
            sum += __shfl_xor_sync(0xffffffffu, sum, m);
            sq  += __shfl_xor_sync(0xffffffffu, sq,  m);
        }
        float mu = sum * (1.f / 128.f);
        float rs = rsqrtf(sq * (1.f / 128.f) - mu * mu + 1e-5f);
#pragma unroll
        for (int c = l; c < 128; c += 8) {
            float v = sZ[c * 32 + p];
            sZ[c * 32 + p] = (v - mu) * rs * lnw[c] + lnb[c];
        }
    }
    __syncthreads();
    {
        u64 acc[16];
#pragma unroll
        for (int q = 0; q < 16; q++) acc[q] = 0ull;
        int j = tid;
        for (int k = 0; k < 128; k++) {
            u64 wv2 = pdup(w1[k * 256 + j]);
            const u64* zp = (const u64*)&sZ[k * 32];
#pragma unroll
            for (int q = 0; q < 16; q++)
                acc[q] = ffma2(zp[q], wv2, acc[q]);
        }
        float bb = b1[j];
#pragma unroll
        for (int q = 0; q < 16; q++) {
            float2 v = unpk(acc[q]);
            float h0 = v.x + bb, h1 = v.y + bb;
            h0 = 0.5f * h0 * (1.f + erff(h0 * 0.70710678118654752f));
            h1 = 0.5f * h1 * (1.f + erff(h1 * 0.70710678118654752f));
            sH[(2 * q) * 256 + j]     = h0;
            sH[(2 * q + 1) * 256 + j] = h1;
        }
    }
    __syncthreads();
    int op = tid & 63;
    int pg = (tid >> 6) * 8;
    u64 acc2[8];
    {
#pragma unroll
        for (int q = 0; q < 8; q++) acc2[q] = 0ull;
        const float2* w2p = (const float2*)w2;
        for (int k = 0; k < 256; k++) {
            float2 wp = w2p[k * 64 + op];
            u64 wv = pack2(wp.x, wp.y);
#pragma unroll
            for (int q = 0; q < 8; q++) {
                u64 h2 = pdup(sH[(pg + q) * 256 + k]);
                acc2[q] = ffma2(h2, wv, acc2[q]);
            }
        }
    }
    __syncthreads();
    {
        float bx = b2[2 * op], by = b2[2 * op + 1];
#pragma unroll
        for (int q = 0; q < 8; q++) {
            float2 v = unpk(acc2[q]);
            *(u64*)&smem[(pg + q) * 130 + 2 * op] = pack2(v.x + bx, v.y + by);
        }
    }
    __syncthreads();
    for (int i = tid; i < 4096; i += 256) {
        int c = i >> 5, p = i & 31;
        int dd = c >> 1, comp = c & 1;
        int gi = base + dd * HW + p;
        float v = smem[p * 130 + (comp ? 64 + dd : dd)];
        out[2 * gi + comp] = v + (comp ? x2i[gi] : x2r[gi]);
    }
}

// -----------------------------------------------------------------------------
extern "C" void kernel_launch(void* const* d_in, const int* in_sizes, int n_in,
                              void* d_out, int out_size)
{
    (void)in_sizes; (void)n_in; (void)out_size;
    const float* x_real  = (const float*)d_in[0];
    const float* x_imag  = (const float*)d_in[1];
    const float* dt      = (const float*)d_in[2];
    const float* ln_s_w  = (const float*)d_in[3];
    const float* ln_s_b  = (const float*)d_in[4];
    const float* ln_t_w  = (const float*)d_in[5];
    const float* ln_t_b  = (const float*)d_in[6];
    const float* ln_m_w  = (const float*)d_in[7];
    const float* ln_m_b  = (const float*)d_in[8];
    const float* cw_r    = (const float*)d_in[9];
    const float* cw_i    = (const float*)d_in[10];
    const float* cb_r    = (const float*)d_in[11];
    const float* cb_i    = (const float*)d_in[12];
    const float* spec_wr = (const float*)d_in[13];
    const float* spec_wi = (const float*)d_in[14];
    const float* gate    = (const float*)d_in[15];
    const float* lam_re  = (const float*)d_in[16];
    const float* lam_im  = (const float*)d_in[17];
    const float* V_re    = (const float*)d_in[18];
    const float* V_im    = (const float*)d_in[19];
    const float* Vinv_re = (const float*)d_in[20];
    const float* Vinv_im = (const float*)d_in[21];
    const float* w1      = (const float*)d_in[22];
    const float* b1      = (const float*)d_in[23];
    const float* w2      = (const float*)d_in[24];
    const float* b2      = (const float*)d_in[25];
    float* out = (float*)d_out;

    float *xnr, *xni, *cr, *ci, *x1r, *x1i, *tnr, *tni, *er, *ei, *x2r, *x2i;
    float2* evo;
    ulonglong2* Ug;
    cudaGetSymbolAddress((void**)&xnr, g_xnr);
    cudaGetSymbolAddress((void**)&xni, g_xni);
    cudaGetSymbolAddress((void**)&cr,  g_cr);
    cudaGetSymbolAddress((void**)&ci,  g_ci);
    cudaGetSymbolAddress((void**)&x1r, g_x1r);
    cudaGetSymbolAddress((void**)&x1i, g_x1i);
    cudaGetSymbolAddress((void**)&tnr, g_tnr);
    cudaGetSymbolAddress((void**)&tni, g_tni);
    cudaGetSymbolAddress((void**)&er,  g_er);
    cudaGetSymbolAddress((void**)&ei,  g_ei);
    cudaGetSymbolAddress((void**)&x2r, g_x2r);
    cudaGetSymbolAddress((void**)&x2i, g_x2i);
    cudaGetSymbolAddress((void**)&evo, g_evo);
    cudaGetSymbolAddress((void**)&Ug,  g_U);

    // ---- spatial stage ----
    wtrans_kernel<<<16, 256>>>(cw_r, cw_i, Ug);
    cnorm_kernel<<<512, 256>>>(x_real, x_imag, ln_s_w, ln_s_b, xnr, xni);
    conv_wino_kernel<<<dim3(16, 8, 32), 256>>>(xnr, xni, Ug, cb_r, cb_i, cr, ci);
    spec_kernel<<<2048, 512>>>(xnr, xni, spec_wr, spec_wi, cr, ci,
                               x_real, x_imag, gate, x1r, x1i);
    // ---- temporal stage ----
    cnorm_kernel<<<512, 256>>>(x1r, x1i, ln_t_w, ln_t_b, tnr, tni);
    cproj_kernel<<<dim3(512, 4), 256>>>(tnr, tni, Vinv_re, Vinv_im,
                                        tnr, tni, er, ei, 0);
    evo_kernel<<<8, 256>>>(dt, lam_re, lam_im, evo);
    scan_kernel<<<2048, 256>>>(er, ei, evo);
    cproj_kernel<<<dim3(512, 4), 256>>>(er, ei, V_re, V_im,
                                        x1r, x1i, x2r, x2i, 1);
    // ---- MLP stage -> final interleaved output ----
    mlp_kernel<<<4096, 256>>>(x2r, x2i, ln_m_w, ln_m_b, w1, b1, w2, b2, out);
}